// round 15
// baseline (speedup 1.0000x reference)
#include <cuda_runtime.h>
#include <cuda_bf16.h>

// Two-node graph pipeline (R14 structure); the cross-block prefix handshake is
// now a single-word publish barrier instead of per-predecessor lookback:
// every block stores its packed total, the LAST publisher bumps g_pub_epoch,
// one thread per block polls that single word (written once -> wakeup), then
// all 32 block sums are read with full MLP and summed from shared memory.
//   K1 build : insert bodies into parity-selected cell grid; last finishing
//              block bumps g_epoch (graph edge publishes it to K2).
//   K2 query+resolve : ring query + fused narrow phase (4-way MLP slot loads,
//              per-hit geometry cached), packed block scan, publish barrier,
//              in-register resolve with exact cutoffs, race-free cleanup.
//
// N=8192, BOX=112, radii in [0.5,1.0) -> rsum < 2.0 -> grid cell 2.0 (56x56);
// all AABB-overlapping pairs lie within the +-1 cell ring.
// Reference semantics reproduced exactly: row-major ascending (i,j) candidate
// order, cutoffs limit_broad=4N (candidates) and limit_narrow=N (hits).

#define MAXN  8192
#define MAXB  (4 * MAXN)
#define GDIM  56
#define NCELL (GDIM * GDIM)
#define CAPC  20            // bodies/cell cap (avg 2.6; Poisson tail safe)
#define CAPR  32            // candidates/row cap (avg ~8; tail safe)
#define NBLK  32
#define NTPB  256
#define NTH   (NBLK * NTPB)

typedef unsigned long long ull;

__device__ unsigned g_done      = 0;         // K1 completion counter (self-resets)
__device__ unsigned g_epoch     = 0;         // +1 per launch by K1's last block
__device__ unsigned g_pub_cnt   = 0;         // K2 publish counter (self-resets)
__device__ unsigned g_pub_epoch = 0;         // +1 per launch by K2's last publisher
__device__ int      g_cellcnt[2][NCELL];     // parity double buffer
__device__ float4   g_cellslot[2][NCELL * CAPC];
__device__ ull      g_bsum[NBLK];            // per-block packed totals

// ---------------------------------------------------------------------------
__global__ void __launch_bounds__(NTPB)
build_kernel(const float2* __restrict__ c, const float* __restrict__ r,
             float* __restrict__ out, int n) {
    const int gid = blockIdx.x * NTPB + threadIdx.x;
    // Epoch is stable during K1: only bumped after ALL blocks finished inserts.
    const unsigned par = *(volatile unsigned*)&g_epoch & 1u;
    if (gid < n) {
        float2 ci = c[gid];
        float  ri = r[gid];
        ((float2*)out)[gid] = ci;
        int cx = min(GDIM - 1, max(0, (int)(ci.x * 0.5f)));
        int cy = min(GDIM - 1, max(0, (int)(ci.y * 0.5f)));
        int cell = cy * GDIM + cx;
        int slot = atomicAdd(&g_cellcnt[par][cell], 1);
        if (slot < CAPC)
            g_cellslot[par][cell * CAPC + slot] =
                make_float4(ci.x, ci.y, ri, __int_as_float(gid));
    }
    __syncthreads();
    if (threadIdx.x == 0) {
        __threadfence();
        unsigned old = atomicAdd(&g_done, 1u);
        if (old == gridDim.x - 1) {       // last block to finish
            g_done = 0;
            atomicAdd(&g_epoch, 1u);      // K2 sees this via the graph edge
        }
    }
}

// ---------------------------------------------------------------------------
__global__ void __launch_bounds__(NTPB)
query_resolve_kernel(const float2* __restrict__ c, const float* __restrict__ r,
                     const int* __restrict__ d_lb, const int* __restrict__ d_ln,
                     float* __restrict__ out, int n) {
    __shared__ ull s_ws[NTPB / 32 + 1];
    __shared__ ull s_sum[NBLK];
    const int t    = threadIdx.x;
    const int lane = t & 31;
    const int wid  = t >> 5;
    const int bid  = blockIdx.x;
    const int gid  = bid * NTPB + t;

    const unsigned E   = *(volatile unsigned*)&g_epoch;  // post-increment value
    const unsigned par = (E - 1u) & 1u;                  // buffer K1 filled

    // ---- query: ring cells -> keys + cached hit geometry ----
    int keys[CAPR];                  // (j<<1) | hit
    float hdx[CAPR], hdy[CAPR], hrs[CAPR];
    unsigned hitmask = 0;
    int cnt = 0;
    float2 ci = make_float2(0.f, 0.f);
    float  ri = 0.f;

#define PROC(b) do {                                                         \
        int   _j  = __float_as_int((b).w);                                   \
        float _rs = ri + (b).z;                                              \
        float _dx = (b).x - ci.x;                                            \
        float _dy = (b).y - ci.y;                                            \
        bool  _acc = (_j > gid) & (fabsf(_dx) <= _rs) & (fabsf(_dy) <= _rs); \
        if (_acc) {                                                          \
            if (cnt < CAPR) {                                                \
                float _d2 = _dx * _dx + _dy * _dy + 1e-12f;                  \
                int _hit = (_d2 < _rs * _rs) ? 1 : 0;                        \
                keys[cnt] = (_j << 1) | _hit;                                \
                hitmask |= (unsigned)_hit << cnt;                            \
                hdx[cnt] = _dx; hdy[cnt] = _dy; hrs[cnt] = _rs;              \
            }                                                                \
            cnt++;                                                           \
        }                                                                    \
    } while (0)

    if (gid < n) {
        ci = c[gid];
        ri = r[gid];
        int cx = min(GDIM - 1, max(0, (int)(ci.x * 0.5f)));
        int cy = min(GDIM - 1, max(0, (int)(ci.y * 0.5f)));
        int cell9[9], cc9[9];
        #pragma unroll
        for (int s = 0; s < 9; s++) {
            int yy = cy + s / 3 - 1;
            int xx = cx + s % 3 - 1;
            bool v = (yy >= 0) & (yy < GDIM) & (xx >= 0) & (xx < GDIM);
            int cell = v ? yy * GDIM + xx : 0;
            cell9[s] = cell;
            cc9[s]   = v ? g_cellcnt[par][cell] : 0;   // 9 independent LDGs
        }
        #pragma unroll
        for (int s = 0; s < 9; s++) {
            int cc = min(cc9[s], CAPC);
            const float4* base = &g_cellslot[par][cell9[s] * CAPC];
            int q = 0;
            for (; q + 3 < cc; q += 4) {         // 4 independent LDG.128s
                float4 b0 = base[q];
                float4 b1 = base[q + 1];
                float4 b2 = base[q + 2];
                float4 b3 = base[q + 3];
                PROC(b0); PROC(b1); PROC(b2); PROC(b3);
            }
            for (; q < cc; q++) {
                float4 b = base[q];
                PROC(b);
            }
        }
        if (cnt > CAPR) cnt = CAPR;
    }
#undef PROC
    const int hitcnt = __popc(hitmask);

    // ---- packed block scan of (cnt<<32 | hitcnt) ----
    ull v = ((ull)cnt << 32) | (unsigned)hitcnt;
    ull incl = v;
    #pragma unroll
    for (int o = 1; o < 32; o <<= 1) {
        ull x = __shfl_up_sync(0xFFFFFFFFu, incl, o);
        if (lane >= o) incl += x;
    }
    if (lane == 31) s_ws[wid] = incl;
    __syncthreads();
    if (wid == 0 && lane == 0) {
        ull run = 0;
        #pragma unroll
        for (int w = 0; w < NTPB / 32; w++) {
            ull x = s_ws[w];
            s_ws[w] = run;
            run += x;
        }
        s_ws[NTPB / 32] = run;
    }
    __syncthreads();
    ull excl = incl - v + s_ws[wid];

    // ---- publish barrier: store total, last publisher bumps g_pub_epoch ----
    if (t == 0) {
        g_bsum[bid] = s_ws[NTPB / 32];
        __threadfence();
        unsigned old = atomicAdd(&g_pub_cnt, 1u);
        if (old == NBLK - 1) {
            g_pub_cnt = 0;
            atomicAdd(&g_pub_epoch, 1u);       // single wakeup word
        }
    }
    // overlap the wait window with useful work:
    const int limitb = min(*d_lb, MAXB);
    const int ln     = *d_ln;
    for (int idx = gid; idx < NCELL; idx += NTH) g_cellcnt[1 - par][idx] = 0;
    if (t == 0) {                               // one thread polls one word
        volatile unsigned* pe = &g_pub_epoch;
        while (*pe != E) __nanosleep(16);
    }
    __syncthreads();

    // all 32 block sums with full MLP, staged through shared
    if (t < NBLK) s_sum[t] = g_bsum[t];
    __syncthreads();
    ull pre = 0;
    #pragma unroll
    for (int b = 0; b < NBLK; b++)
        if (b < bid) pre += s_sum[b];

    const ull tot  = pre + excl;
    const int offc = (int)(tot >> 32);
    const int offh = (int)(tot & 0xFFFFFFFFu);

    // ---- resolve: hit-bit walk, exact cutoffs, zero reloads ----
    // Broad cutoff: sorted rank < limitb - offc. Dropped candidates are always
    // the highest ranks, so unmasked prefix sums stay exact for emitters.
    if (gid < n && hitmask && offc < limitb) {
        const int survive = min(cnt, limitb - offc);
        float2 neg = make_float2(0.f, 0.f);
        unsigned m = hitmask;
        while (m) {
            int k = __ffs(m) - 1;
            m &= m - 1;
            int key = keys[k];
            int rank = 0, hrank = 0;
            #pragma unroll 4
            for (int q = 0; q < cnt; q++) {       // branch-free rank loop
                int kq = keys[q];
                int lt = (kq < key) ? 1 : 0;      // distinct j -> strict order
                rank  += lt;
                hrank += lt & kq;                 // lt && hit-bit of q
            }
            if (rank >= survive) continue;        // broad cutoff
            if (offh + hrank >= ln) continue;     // narrow cutoff
            float dx = hdx[k], dy = hdy[k], rs = hrs[k];
            float dist = sqrtf(dx * dx + dy * dy + 1e-12f);
            float sc = 0.5f * (rs - dist) / dist;
            float ddx = sc * dx, ddy = sc * dy;
            int jv = key >> 1;
            neg.x -= ddx; neg.y -= ddy;
            atomicAdd(&out[2 * jv + 0], ddx);
            atomicAdd(&out[2 * jv + 1], ddy);
        }
        if (neg.x != 0.f || neg.y != 0.f) {
            atomicAdd(&out[2 * gid + 0], neg.x);
            atomicAdd(&out[2 * gid + 1], neg.y);
        }
    }
}

// ---------------------------------------------------------------------------
extern "C" void kernel_launch(void* const* d_in, const int* in_sizes, int n_in,
                              void* d_out, int out_size) {
    const float2* centers = (const float2*)d_in[0];
    const float*  radii   = (const float*)d_in[1];
    const int*    d_lb    = (const int*)d_in[2];
    const int*    d_ln    = (const int*)d_in[3];
    const int n = in_sizes[1];
    float* out = (float*)d_out;

    build_kernel<<<NBLK, NTPB>>>(centers, radii, out, n);
    query_resolve_kernel<<<NBLK, NTPB>>>(centers, radii, d_lb, d_ln, out, n);
}